// round 3
// baseline (speedup 1.0000x reference)
#include <cuda_runtime.h>

#define NR 8192
#define NT 8192
#define RB 64
#define CB 64
#define GRIDC 592          // 148 SMs * 4 persistent CTAs

// Scratch (device globals — no allocation allowed)
__device__ float g_A[NR * CB];        // per-row col-block sums, 2 MB

// ---------------------------------------------------------------------------
// Zero g_A (atomics accumulate into it each replay)
// ---------------------------------------------------------------------------
__global__ void k_zero() {
    float4* p = (float4*)g_A;
    int i = blockIdx.x * blockDim.x + threadIdx.x;          // 32768 threads
#pragma unroll
    for (int s = 0; s < 4; s++) p[i + 32768 * s] = make_float4(0, 0, 0, 0);
}

// ---------------------------------------------------------------------------
// Per-row column-block sums: the 256 MB bandwidth pass.
// Persistent CTAs (592 x 256 thr). Warp w owns cols [1024w, 1024w+1024).
// Fully coalesced float4 loads kept in registers; warp-uniform segment walk:
//   - window (128 cols) with no block boundary -> per-lane tree add
//   - boundary window -> predicated split + shfl butterfly + one REDG flush
// No shared staging, no barriers in the row loop -> loads stay in flight.
// ---------------------------------------------------------------------------
__global__ __launch_bounds__(256) void k_colsum(const float* __restrict__ X,
                                                const int* __restrict__ col_ids) {
    __shared__ int scum[CB + 1];

    const int tid  = threadIdx.x;
    const int lane = tid & 31;
    const int w    = tid >> 5;

    // Build col_cum by transition detection over sorted ids (each scum entry
    // written by exactly one thread).
    if (tid == 0) scum[CB] = NT;
    for (int i = tid; i < NT; i += 256) {
        int cur  = col_ids[i];
        int prev = i ? col_ids[i - 1] : -1;
        for (int b = prev; b < cur; b++) scum[b + 1] = i;
    }
    __syncthreads();

    // Block containing the warp's first column (warp-uniform)
    const int base_w = w << 10;
    int lo = 0, hi = CB;
    while (lo < hi) {
        int mid = (lo + hi + 1) >> 1;
        if (scum[mid] <= base_w) lo = mid; else hi = mid - 1;
    }
    const int cb0 = lo;
    const int nb0 = scum[lo + 1];

    const int f0 = (w << 8) + lane;     // this lane's first float4 index in row

    for (int row = blockIdx.x; row < NR; row += GRIDC) {
        const float4* Xr = (const float4*)X + row * (NT / 4);
        float4 v[8];
#pragma unroll
        for (int s = 0; s < 8; s++) v[s] = Xr[f0 + 32 * s];   // 8 LDG.128 batched

        float* gA = g_A + row * CB;
        int   cb  = cb0;
        int   nb  = nb0;
        float acc = 0.0f;

#pragma unroll
        for (int s = 0; s < 8; s++) {
            const int   W0 = base_w + (s << 7);      // window start (uniform)
            const int   c  = W0 + (lane << 2);       // lane's first col
            const float4 q = v[s];

            if (nb >= W0 + 128) {
                // whole window inside current block
                acc += (q.x + q.y) + (q.z + q.w);
            } else {
                int L = 0;                            // cols < L already consumed
                while (nb < W0 + 128) {               // warp-uniform loop
                    acc += ((c + 0 >= L && c + 0 < nb) ? q.x : 0.0f)
                         + ((c + 1 >= L && c + 1 < nb) ? q.y : 0.0f)
                         + ((c + 2 >= L && c + 2 < nb) ? q.z : 0.0f)
                         + ((c + 3 >= L && c + 3 < nb) ? q.w : 0.0f);
                    // flush block cb (all 32 lanes converged)
                    float t = acc;
                    t += __shfl_xor_sync(0xFFFFFFFFu, t, 16);
                    t += __shfl_xor_sync(0xFFFFFFFFu, t, 8);
                    t += __shfl_xor_sync(0xFFFFFFFFu, t, 4);
                    t += __shfl_xor_sync(0xFFFFFFFFu, t, 2);
                    t += __shfl_xor_sync(0xFFFFFFFFu, t, 1);
                    if (lane == 0 && t != 0.0f) atomicAdd(&gA[cb], t);
                    acc = 0.0f;
                    L  = nb;
                    cb++;
                    nb = scum[cb + 1];
                }
                // leftover of this window belongs to the new current block
                acc += ((c + 0 >= L) ? q.x : 0.0f) + ((c + 1 >= L) ? q.y : 0.0f)
                     + ((c + 2 >= L) ? q.z : 0.0f) + ((c + 3 >= L) ? q.w : 0.0f);
            }
        }
        // flush the final block of this warp's range
        float t = acc;
        t += __shfl_xor_sync(0xFFFFFFFFu, t, 16);
        t += __shfl_xor_sync(0xFFFFFFFFu, t, 8);
        t += __shfl_xor_sync(0xFFFFFFFFu, t, 4);
        t += __shfl_xor_sync(0xFFFFFFFFu, t, 2);
        t += __shfl_xor_sync(0xFFFFFFFFu, t, 1);
        if (lane == 0 && t != 0.0f) atomicAdd(&gA[cb], t);
    }
}

// ---------------------------------------------------------------------------
// Final: derive row/col cumsums from sorted ids (transition scans), segment-
// sum g_A over rows (deterministic 4-way split), mean, 1->3->3->1 ReLU MLP,
// sigmoid, tail cumsum outputs. Grid: RB CTAs x 256 threads.
// ---------------------------------------------------------------------------
__global__ void k_final(const int* __restrict__ row_ids,
                        const int* __restrict__ col_ids,
                        const float* __restrict__ W1, const float* __restrict__ b1,
                        const float* __restrict__ W2, const float* __restrict__ b2,
                        const float* __restrict__ W3, const float* __restrict__ b3,
                        float* __restrict__ out, int out_size) {
    __shared__ int   rcum[RB + 1];
    __shared__ int   ccum[CB + 1];
    __shared__ float part[4][CB];

    const int tid = threadIdx.x;
    if (tid == 0) { rcum[RB] = NR; ccum[CB] = NT; }
    for (int i = tid; i < NR; i += 256) {
        int cur  = row_ids[i];
        int prev = i ? row_ids[i - 1] : -1;
        for (int b = prev; b < cur; b++) rcum[b + 1] = i;
    }
    for (int i = tid; i < NT; i += 256) {
        int cur  = col_ids[i];
        int prev = i ? col_ids[i - 1] : -1;
        for (int b = prev; b < cur; b++) ccum[b + 1] = i;
    }
    __syncthreads();

    const int rb = blockIdx.x;
    const int cb = tid & 63;
    const int q  = tid >> 6;

    const int r0 = rcum[rb];
    const int r1 = rcum[rb + 1];
    const int n  = r1 - r0;
    const int qs = r0 + (n * q) / 4;
    const int qe = r0 + (n * (q + 1)) / 4;

    float s = 0.0f;
    for (int r = qs; r < qe; r++) s += g_A[r * CB + cb];   // coalesced over cb
    part[q][cb] = s;
    __syncthreads();

    if (tid < CB) {
        s = part[0][cb] + part[1][cb] + part[2][cb] + part[3][cb];

        const float rcount = (float)n;
        const float ccount = (float)(ccum[cb + 1] - ccum[cb]);
        const float x = s / (rcount * ccount);

        float h1[3], h2[3];
#pragma unroll
        for (int k = 0; k < 3; k++) h1[k] = fmaxf(x * W1[k] + b1[k], 0.0f);
#pragma unroll
        for (int j = 0; j < 3; j++) {
            float z = b2[j];
#pragma unroll
            for (int k = 0; k < 3; k++) z += h1[k] * W2[k * 3 + j];
            h2[j] = fmaxf(z, 0.0f);
        }
        float z = b3[0];
#pragma unroll
        for (int j = 0; j < 3; j++) z += h2[j] * W3[j];

        out[rb * CB + cb] = 1.0f / (1.0f + expf(-z));
    }

    // Tail outputs: row_cumsum[65], col_cumsum[65] as float
    if (rb == 0 && out_size >= RB * CB + 2 * (RB + 1)) {
        if (tid <= RB)                 out[RB * CB + tid] = (float)rcum[tid];
        if (tid >= 128 && tid <= 128 + CB)
            out[RB * CB + (RB + 1) + (tid - 128)] = (float)ccum[tid - 128];
    }
}

// ---------------------------------------------------------------------------
extern "C" void kernel_launch(void* const* d_in, const int* in_sizes, int n_in,
                              void* d_out, int out_size) {
    const float* X       = (const float*)d_in[0];
    const int*   row_ids = (const int*)d_in[1];
    const int*   col_ids = (const int*)d_in[2];
    const float* W1      = (const float*)d_in[3];
    const float* b1      = (const float*)d_in[4];
    const float* W2      = (const float*)d_in[5];
    const float* b2      = (const float*)d_in[6];
    const float* W3      = (const float*)d_in[7];
    const float* b3      = (const float*)d_in[8];
    float* out = (float*)d_out;

    k_zero<<<128, 256>>>();
    k_colsum<<<GRIDC, 256>>>(X, col_ids);
    k_final<<<RB, 256>>>(row_ids, col_ids, W1, b1, W2, b2, W3, b3, out, out_size);
}

// round 4
// speedup vs baseline: 1.4720x; 1.4720x over previous
#include <cuda_runtime.h>

#define NR 8192
#define NT 8192
#define RB 64
#define CB 64
#define GRIDC 592          // 148 SMs * 4 CTAs

// 16 KB accumulator. Zero-initialized at load; k_final re-zeros it after
// consuming, so every kernel_launch call starts from zeros (graph-replay safe).
__device__ float g_B[RB * CB];

__device__ __forceinline__ int bsearch_ge(const int* __restrict__ ids, int n, int b) {
    // first i with ids[i] >= b (ids sorted ascending)
    int lo = 0, hi = n;
    while (lo < hi) { int mid = (lo + hi) >> 1; if (ids[mid] < b) lo = mid + 1; else hi = mid; }
    return lo;
}

// ---------------------------------------------------------------------------
// The 256 MB bandwidth pass. Persistent CTAs; warp w owns cols [1024w,+1024).
// Per row: coalesced float4 LDG -> XOR-swizzled smem (conflict-free STS.128 &
// LDS.128) -> prefetch next row's LDGs -> per-lane contiguous-32-col segment
// walk -> direct atomicAdd flush into g_B[row_block][col_block].
// No CTA barriers in the loop; reduce overlaps next row's DRAM latency.
// ---------------------------------------------------------------------------
__global__ __launch_bounds__(256, 4) void k_colsum(const float* __restrict__ X,
                                                   const int* __restrict__ row_ids,
                                                   const int* __restrict__ col_ids) {
    __shared__ float4 sbuf[8][256];     // 32 KB
    __shared__ int    scum[CB + 1];

    const int tid  = threadIdx.x;
    const int lane = tid & 31;
    const int w    = tid >> 5;

    if (tid <= CB) scum[tid] = (tid == 0) ? 0 : (tid == CB ? NT : bsearch_ge(col_ids, NT, tid));
    __syncthreads();

    // Block containing this lane's first column (chunk = 32 contiguous cols)
    const int c0 = (w << 10) + (lane << 5);
    int lo = 0, hi = CB;
    while (lo < hi) {
        int mid = (lo + hi + 1) >> 1;
        if (scum[mid] <= c0) lo = mid; else hi = mid - 1;
    }
    const int cb0 = lo;
    const int f0  = (w << 8) + lane;    // lane's first float4 index in the row

    int row = blockIdx.x;
    const float4* Xr = (const float4*)X + (size_t)row * (NT / 4);
    float4 v[8];
#pragma unroll
    for (int s = 0; s < 8; s++) v[s] = Xr[f0 + 32 * s];
    int rb = row_ids[row];

    while (true) {
        // stage current row (swizzle: phys = f ^ ((f>>3)&7))
#pragma unroll
        for (int s = 0; s < 8; s++) {
            int f = lane + 32 * s;
            sbuf[w][f ^ ((f >> 3) & 7)] = v[s];
        }
        __syncwarp();

        // prefetch next row while we reduce this one
        const int next = row + GRIDC;
        int rb_next = 0;
        if (next < NR) {
            const float4* Xn = (const float4*)X + (size_t)next * (NT / 4);
#pragma unroll
            for (int s = 0; s < 8; s++) v[s] = Xn[f0 + 32 * s];
            rb_next = row_ids[next];
        }

        // reduce lane's contiguous cols [c0, c0+32) out of smem
        float* gB = g_B + rb * CB;
        int   cb  = cb0;
        int   nb  = scum[cb0 + 1];
        float acc = 0.0f;
#pragma unroll
        for (int j = 0; j < 8; j++) {
            int f = (lane << 3) + j;              // (f>>3)&7 == lane&7
            float4 q = sbuf[w][f ^ (lane & 7)];
            int c = c0 + (j << 2);
            if (c + 4 <= nb) {
                acc += (q.x + q.y) + (q.z + q.w);
            } else {
                float e0 = q.x, e1 = q.y, e2 = q.z, e3 = q.w;
                float e[4] = {e0, e1, e2, e3};
#pragma unroll
                for (int k = 0; k < 4; k++) {
                    while (c + k >= nb) {
                        if (acc != 0.0f) atomicAdd(&gB[cb], acc);
                        acc = 0.0f;
                        cb++;
                        nb = scum[cb + 1];
                    }
                    acc += e[k];
                }
            }
        }
        if (acc != 0.0f) atomicAdd(&gB[cb], acc);
        __syncwarp();                   // protect sbuf before next overwrite

        if (next >= NR) break;
        row = next;
        rb  = rb_next;
    }
}

// ---------------------------------------------------------------------------
// Final: boundaries via binary search on sorted ids, block mean from g_B,
// 1->3->3->1 ReLU MLP, sigmoid, cumsum tails; then re-zero g_B slice.
// Grid: RB CTAs x 128 threads.
// ---------------------------------------------------------------------------
__global__ void k_final(const int* __restrict__ row_ids,
                        const int* __restrict__ col_ids,
                        const float* __restrict__ W1, const float* __restrict__ b1,
                        const float* __restrict__ W2, const float* __restrict__ b2,
                        const float* __restrict__ W3, const float* __restrict__ b3,
                        float* __restrict__ out, int out_size) {
    __shared__ int rcum[RB + 1];
    __shared__ int ccum[CB + 1];

    const int t  = threadIdx.x;
    const int rb = blockIdx.x;

    if (t <= RB) {
        rcum[t] = (t == 0) ? 0 : (t == RB ? NR : bsearch_ge(row_ids, NR, t));
        ccum[t] = (t == 0) ? 0 : (t == CB ? NT : bsearch_ge(col_ids, NT, t));
    }
    __syncthreads();

    if (t < CB) {
        const float s      = g_B[rb * CB + t];
        const float rcount = (float)(rcum[rb + 1] - rcum[rb]);
        const float ccount = (float)(ccum[t + 1] - ccum[t]);
        const float x      = s / (rcount * ccount);

        float h1[3], h2[3];
#pragma unroll
        for (int k = 0; k < 3; k++) h1[k] = fmaxf(x * W1[k] + b1[k], 0.0f);
#pragma unroll
        for (int j = 0; j < 3; j++) {
            float z = b2[j];
#pragma unroll
            for (int k = 0; k < 3; k++) z += h1[k] * W2[k * 3 + j];
            h2[j] = fmaxf(z, 0.0f);
        }
        float z = b3[0];
#pragma unroll
        for (int j = 0; j < 3; j++) z += h2[j] * W3[j];

        out[rb * CB + t] = 1.0f / (1.0f + expf(-z));
    }
    __syncthreads();
    if (t < CB) g_B[rb * CB + t] = 0.0f;   // restore invariant for next replay

    if (rb == 0 && out_size >= RB * CB + 2 * (RB + 1) && t <= RB) {
        out[RB * CB + t]            = (float)rcum[t];
        out[RB * CB + (RB + 1) + t] = (float)ccum[t];
    }
}

// ---------------------------------------------------------------------------
extern "C" void kernel_launch(void* const* d_in, const int* in_sizes, int n_in,
                              void* d_out, int out_size) {
    const float* X       = (const float*)d_in[0];
    const int*   row_ids = (const int*)d_in[1];
    const int*   col_ids = (const int*)d_in[2];
    const float* W1      = (const float*)d_in[3];
    const float* b1      = (const float*)d_in[4];
    const float* W2      = (const float*)d_in[5];
    const float* b2      = (const float*)d_in[6];
    const float* W3      = (const float*)d_in[7];
    const float* b3      = (const float*)d_in[8];
    float* out = (float*)d_out;

    k_colsum<<<GRIDC, 256>>>(X, row_ids, col_ids);
    k_final<<<RB, 128>>>(row_ids, col_ids, W1, b1, W2, b2, W3, b3, out, out_size);
}